// round 6
// baseline (speedup 1.0000x reference)
#include <cuda_runtime.h>
#include <math.h>
#include <float.h>

#define BATCH 2
#define NPTS  8192
#define KNB   16
#define NSEG  256
#define DIM   768
#define H1DIM 128
#define H2DIM 256

// ---------------- device scratch (static allocations, allowed) ----------------
static __device__ float4 g_c4[BATCH * NPTS];                 // xyz + |c|^2
static __device__ int    g_idx[BATCH * NPTS * KNB];          // knn indices (local per batch)
static __device__ float  g_hbar[BATCH * NPTS * H2DIM];       // mean_k relu(h2)
static __device__ float  g_sums[BATCH * NSEG * DIM];         // segment sums of pc
static __device__ float  g_counts[BATCH * NSEG];
static __device__ float  g_means[BATCH * NSEG * DIM];
static __device__ float  g_lin1[BATCH * NSEG * DIM];         // means @ Wa + ba
static __device__ float  g_lnr[BATCH * NSEG * DIM];          // relu(LN(lin1))
static __device__ float  g_agg[BATCH * NSEG * DIM];          // lnr @ Wb + bb

// ---------------- small prep kernels ----------------
__global__ void pack_c4_kernel(const float* __restrict__ coords) {
    int i = blockIdx.x * 256 + threadIdx.x;
    if (i >= BATCH * NPTS) return;
    float x = coords[3 * i + 0];
    float y = coords[3 * i + 1];
    float z = coords[3 * i + 2];
    g_c4[i] = make_float4(x, y, z, x * x + y * y + z * z);
}

__global__ void zero_kernel() {
    int i = blockIdx.x * 256 + threadIdx.x;
    if (i < BATCH * NSEG * DIM) g_sums[i] = 0.0f;
    if (i < BATCH * NSEG) g_counts[i] = 0.0f;
}

__global__ void count_kernel(const int* __restrict__ labels) {
    int i = blockIdx.x * 256 + threadIdx.x;
    if (i >= BATCH * NPTS) return;
    atomicAdd(&g_counts[(i >> 13) * NSEG + labels[i]], 1.0f);
}

// ---------------- KNN: one warp per query, per-lane top-16 in registers ----------------
__global__ void knn_kernel() {
    __shared__ float4 tile[2048];
    int b = blockIdx.y;
    int warp = threadIdx.x >> 5;
    int lane = threadIdx.x & 31;
    int q = blockIdx.x * 8 + warp;

    float4 qc = g_c4[b * NPTS + q];
    float ax = -2.0f * qc.x, ay = -2.0f * qc.y, az = -2.0f * qc.z;

    float kd[16];
    int   ki[16];
#pragma unroll
    for (int u = 0; u < 16; u++) { kd[u] = FLT_MAX; ki[u] = 0; }
    float kmax = FLT_MAX;
    int   kpos = 0;

    for (int t = 0; t < 4; t++) {
        __syncthreads();
        for (int i = threadIdx.x; i < 2048; i += 256)
            tile[i] = g_c4[b * NPTS + t * 2048 + i];
        __syncthreads();
        for (int it = 0; it < 64; it++) {
            int j = it * 32 + lane;
            float4 c = tile[j];
            // key = |c|^2 - 2 q.c  (monotone in squared distance)
            float key = fmaf(ax, c.x, fmaf(ay, c.y, fmaf(az, c.z, c.w)));
            if (key < kmax) {
                int gidx = t * 2048 + j;
#pragma unroll
                for (int u = 0; u < 16; u++)
                    if (u == kpos) { kd[u] = key; ki[u] = gidx; }
                kmax = kd[0]; kpos = 0;
#pragma unroll
                for (int u = 1; u < 16; u++)
                    if (kd[u] > kmax) { kmax = kd[u]; kpos = u; }
            }
        }
    }

    // merge 32 lanes x top-16 -> global top-16 (order within K irrelevant: mean over K)
    for (int r = 0; r < 16; r++) {
        float lmin = kd[0]; int lidx = ki[0]; int lpos = 0;
#pragma unroll
        for (int u = 1; u < 16; u++)
            if (kd[u] < lmin) { lmin = kd[u]; lidx = ki[u]; lpos = u; }
        float v = lmin; int wl = lane;
#pragma unroll
        for (int off = 16; off > 0; off >>= 1) {
            float ov = __shfl_xor_sync(0xffffffffu, v, off);
            int   ol = __shfl_xor_sync(0xffffffffu, wl, off);
            if (ov < v || (ov == v && ol < wl)) { v = ov; wl = ol; }
        }
        int chosen = __shfl_sync(0xffffffffu, lidx, wl);
        if (lane == wl) {
#pragma unroll
            for (int u = 0; u < 16; u++)
                if (u == lpos) kd[u] = FLT_MAX;
        }
        if (lane == r) g_idx[(b * NPTS + q) * KNB + r] = chosen;
    }
}

// ---------------- fused geometric features + MLP layers 1,2 + mean over K ----------------
// block = 256 threads, handles 4 points (64 rows of (point,k))
__global__ void mlp12_kernel(const float* __restrict__ W1, const float* __restrict__ b1,
                             const float* __restrict__ W2, const float* __restrict__ b2) {
    __shared__ float h1t[H1DIM * 64];   // [channel][row], 32 KB
    __shared__ float w2s[32 * 64];      // [kk][col] subtile, 8 KB
    __shared__ float w1s[7 * H1DIM];
    __shared__ float b1s[H1DIM];
    __shared__ float b2s[H2DIM];
    int tid = threadIdx.x;
    int blk = blockIdx.x;

    for (int i = tid; i < 7 * H1DIM; i += 256) w1s[i] = W1[i];
    if (tid < H1DIM) b1s[tid] = b1[tid];
    b2s[tid] = b2[tid];
    __syncthreads();

    // phase 1: features + layer1 (each thread: one row, 32 of 128 channels)
    {
        int row = tid >> 2;       // 0..63
        int qq  = tid & 3;        // channel quarter
        int pg  = blk * 4 + (row >> 4);      // flat point idx in [0, B*N)
        int bb  = pg >> 13;
        int k   = row & 15;
        int nb  = g_idx[pg * KNB + k];
        float4 sc = g_c4[pg];
        float4 nc = g_c4[bb * NPTS + nb];
        float dx = nc.x - sc.x, dy = nc.y - sc.y, dz = nc.z - sc.z;
        float f0 = sqrtf(dx * dx + dy * dy + dz * dz);
        float f4 = atan2f(dy, dx);
        float f5 = atan2f(dz, dx);
        float f6 = atan2f(dz, dy);
        int cbase = qq * 32;
#pragma unroll 8
        for (int c0 = 0; c0 < 32; c0++) {
            int c = cbase + c0;
            float acc = b1s[c];
            acc = fmaf(f0, w1s[c], acc);
            acc = fmaf(dx, w1s[1 * H1DIM + c], acc);
            acc = fmaf(dy, w1s[2 * H1DIM + c], acc);
            acc = fmaf(dz, w1s[3 * H1DIM + c], acc);
            acc = fmaf(f4, w1s[4 * H1DIM + c], acc);
            acc = fmaf(f5, w1s[5 * H1DIM + c], acc);
            acc = fmaf(f6, w1s[6 * H1DIM + c], acc);
            h1t[c * 64 + row] = fmaxf(acc, 0.0f);
        }
    }
    __syncthreads();

    // phase 2: h2 = relu(h1 @ W2 + b2), mean over k within each point
    int ci = tid >> 4;   // 0..15 col group
    int ri = tid & 15;   // 0..15 row group (4 rows each)
    for (int t = 0; t < 4; t++) {
        float acc[4][4];
#pragma unroll
        for (int i = 0; i < 4; i++)
#pragma unroll
            for (int j = 0; j < 4; j++) acc[i][j] = 0.0f;

        for (int ks = 0; ks < 4; ks++) {
            __syncthreads();
            for (int i = tid; i < 2048; i += 256) {
                int kk = i >> 6, c = i & 63;
                w2s[i] = W2[(ks * 32 + kk) * H2DIM + t * 64 + c];
            }
            __syncthreads();
#pragma unroll
            for (int kk = 0; kk < 32; kk++) {
                float4 av = *(const float4*)&h1t[(ks * 32 + kk) * 64 + ri * 4];
                float4 bv = *(const float4*)&w2s[kk * 64 + ci * 4];
                acc[0][0] += av.x * bv.x; acc[0][1] += av.x * bv.y; acc[0][2] += av.x * bv.z; acc[0][3] += av.x * bv.w;
                acc[1][0] += av.y * bv.x; acc[1][1] += av.y * bv.y; acc[1][2] += av.y * bv.z; acc[1][3] += av.y * bv.w;
                acc[2][0] += av.z * bv.x; acc[2][1] += av.z * bv.y; acc[2][2] += av.z * bv.z; acc[2][3] += av.z * bv.w;
                acc[3][0] += av.w * bv.x; acc[3][1] += av.w * bv.y; acc[3][2] += av.w * bv.z; acc[3][3] += av.w * bv.w;
            }
        }
        // relu(+b2) per row, then sum rows (4 local + shuffle over ri&3)
        float bv0 = b2s[t * 64 + ci * 4 + 0];
        float bv1 = b2s[t * 64 + ci * 4 + 1];
        float bv2 = b2s[t * 64 + ci * 4 + 2];
        float bv3 = b2s[t * 64 + ci * 4 + 3];
        float s0 = 0.f, s1 = 0.f, s2 = 0.f, s3 = 0.f;
#pragma unroll
        for (int i = 0; i < 4; i++) {
            s0 += fmaxf(acc[i][0] + bv0, 0.0f);
            s1 += fmaxf(acc[i][1] + bv1, 0.0f);
            s2 += fmaxf(acc[i][2] + bv2, 0.0f);
            s3 += fmaxf(acc[i][3] + bv3, 0.0f);
        }
        s0 += __shfl_xor_sync(0xffffffffu, s0, 1); s0 += __shfl_xor_sync(0xffffffffu, s0, 2);
        s1 += __shfl_xor_sync(0xffffffffu, s1, 1); s1 += __shfl_xor_sync(0xffffffffu, s1, 2);
        s2 += __shfl_xor_sync(0xffffffffu, s2, 1); s2 += __shfl_xor_sync(0xffffffffu, s2, 2);
        s3 += __shfl_xor_sync(0xffffffffu, s3, 1); s3 += __shfl_xor_sync(0xffffffffu, s3, 2);
        if ((ri & 3) == 0) {
            int p = blk * 4 + (ri >> 2);
            const float inv = 1.0f / 16.0f;
            float4 o = make_float4(s0 * inv, s1 * inv, s2 * inv, s3 * inv);
            *(float4*)&g_hbar[p * H2DIM + t * 64 + ci * 4] = o;
        }
    }
}

// ---------------- generic 64x64 tiled fp32 GEMM core ----------------
struct GemmSmem { float As[64][17]; float Bs[16][64]; };

__device__ __forceinline__ void gemm_tile(const float* __restrict__ A,
                                          const float* __restrict__ Bm,
                                          int Kk, int Nn, int r0, int c0,
                                          GemmSmem* sm, float acc[4][4]) {
    int tid = threadIdx.x, tx = tid & 15, ty = tid >> 4;
    for (int k0 = 0; k0 < Kk; k0 += 16) {
        for (int i = tid; i < 1024; i += 256) {
            int r = i >> 4, kk = i & 15;
            sm->As[r][kk] = A[(r0 + r) * Kk + k0 + kk];
        }
        for (int i = tid; i < 1024; i += 256) {
            int kk = i >> 6, c = i & 63;
            sm->Bs[kk][c] = Bm[(k0 + kk) * Nn + c0 + c];
        }
        __syncthreads();
#pragma unroll
        for (int kk = 0; kk < 16; kk++) {
            float a0 = sm->As[ty * 4 + 0][kk];
            float a1 = sm->As[ty * 4 + 1][kk];
            float a2 = sm->As[ty * 4 + 2][kk];
            float a3 = sm->As[ty * 4 + 3][kk];
            float4 bf = *(const float4*)&sm->Bs[kk][tx * 4];
            acc[0][0] += a0 * bf.x; acc[0][1] += a0 * bf.y; acc[0][2] += a0 * bf.z; acc[0][3] += a0 * bf.w;
            acc[1][0] += a1 * bf.x; acc[1][1] += a1 * bf.y; acc[1][2] += a1 * bf.z; acc[1][3] += a1 * bf.w;
            acc[2][0] += a2 * bf.x; acc[2][1] += a2 * bf.y; acc[2][2] += a2 * bf.z; acc[2][3] += a2 * bf.w;
            acc[3][0] += a3 * bf.x; acc[3][1] += a3 * bf.y; acc[3][2] += a3 * bf.z; acc[3][3] += a3 * bf.w;
        }
        __syncthreads();
    }
}

// pc = hbar @ W3 + b3 ; also scatter-add into segment sums
__global__ void gemm_pc_kernel(const float* __restrict__ W3, const float* __restrict__ b3,
                               const int* __restrict__ labels, float* __restrict__ out) {
    __shared__ GemmSmem sm;
    int r0 = blockIdx.y * 64, c0 = blockIdx.x * 64;
    float acc[4][4];
#pragma unroll
    for (int i = 0; i < 4; i++)
#pragma unroll
        for (int j = 0; j < 4; j++) acc[i][j] = 0.0f;
    gemm_tile(g_hbar, W3, H2DIM, DIM, r0, c0, &sm, acc);
    int tid = threadIdx.x, tx = tid & 15, ty = tid >> 4;
#pragma unroll
    for (int i = 0; i < 4; i++) {
        int row = r0 + ty * 4 + i;
        int lbl = labels[row];
        int base = (row >> 13) * NSEG * DIM + lbl * DIM;
#pragma unroll
        for (int j = 0; j < 4; j++) {
            int col = c0 + tx * 4 + j;
            float v = acc[i][j] + b3[col];
            out[row * DIM + col] = v;
            atomicAdd(&g_sums[base + col], v);
        }
    }
}

__global__ void means_kernel() {
    int i = blockIdx.x * 256 + threadIdx.x;
    if (i >= BATCH * NSEG * DIM) return;
    g_means[i] = g_sums[i] / fmaxf(g_counts[i / DIM], 1.0f);
}

__global__ void gemm_a_kernel(const float* __restrict__ Wa, const float* __restrict__ ba) {
    __shared__ GemmSmem sm;
    int r0 = blockIdx.y * 64, c0 = blockIdx.x * 64;
    float acc[4][4];
#pragma unroll
    for (int i = 0; i < 4; i++)
#pragma unroll
        for (int j = 0; j < 4; j++) acc[i][j] = 0.0f;
    gemm_tile(g_means, Wa, DIM, DIM, r0, c0, &sm, acc);
    int tid = threadIdx.x, tx = tid & 15, ty = tid >> 4;
#pragma unroll
    for (int i = 0; i < 4; i++)
#pragma unroll
        for (int j = 0; j < 4; j++) {
            int row = r0 + ty * 4 + i, col = c0 + tx * 4 + j;
            g_lin1[row * DIM + col] = acc[i][j] + ba[col];
        }
}

__global__ void ln_relu_kernel(const float* __restrict__ lng, const float* __restrict__ lnb) {
    int row = blockIdx.x, tid = threadIdx.x;
    __shared__ float sh[8];
    const float* a = &g_lin1[row * DIM];
    float s = 0.0f;
    for (int c = tid; c < DIM; c += 256) s += a[c];
#pragma unroll
    for (int o = 16; o > 0; o >>= 1) s += __shfl_xor_sync(0xffffffffu, s, o);
    if ((tid & 31) == 0) sh[tid >> 5] = s;
    __syncthreads();
    float mu = 0.0f;
#pragma unroll
    for (int w = 0; w < 8; w++) mu += sh[w];
    mu *= (1.0f / DIM);
    __syncthreads();
    float vs = 0.0f;
    for (int c = tid; c < DIM; c += 256) { float d = a[c] - mu; vs += d * d; }
#pragma unroll
    for (int o = 16; o > 0; o >>= 1) vs += __shfl_xor_sync(0xffffffffu, vs, o);
    if ((tid & 31) == 0) sh[tid >> 5] = vs;
    __syncthreads();
    float var = 0.0f;
#pragma unroll
    for (int w = 0; w < 8; w++) var += sh[w];
    var *= (1.0f / DIM);
    float rstd = rsqrtf(var + 1e-5f);
    for (int c = tid; c < DIM; c += 256) {
        float x = (a[c] - mu) * rstd * lng[c] + lnb[c];
        g_lnr[row * DIM + c] = fmaxf(x, 0.0f);
    }
}

__global__ void gemm_b_kernel(const float* __restrict__ Wb, const float* __restrict__ bb) {
    __shared__ GemmSmem sm;
    int r0 = blockIdx.y * 64, c0 = blockIdx.x * 64;
    float acc[4][4];
#pragma unroll
    for (int i = 0; i < 4; i++)
#pragma unroll
        for (int j = 0; j < 4; j++) acc[i][j] = 0.0f;
    gemm_tile(g_lnr, Wb, DIM, DIM, r0, c0, &sm, acc);
    int tid = threadIdx.x, tx = tid & 15, ty = tid >> 4;
#pragma unroll
    for (int i = 0; i < 4; i++)
#pragma unroll
        for (int j = 0; j < 4; j++) {
            int row = r0 + ty * 4 + i, col = c0 + tx * 4 + j;
            g_agg[row * DIM + col] = acc[i][j] + bb[col];
        }
}

__global__ void mix_kernel(const int* __restrict__ labels, float* __restrict__ out) {
    int row = blockIdx.y;
    int col = blockIdx.x * 256 + threadIdx.x;
    int lbl = labels[row];
    int bs = (row >> 13) * NSEG + lbl;
    float pc = out[row * DIM + col];
    float res = pc;
    if (g_counts[bs] >= 2.0f)
        res = 0.8f * pc + 0.2f * g_agg[bs * DIM + col];
    out[row * DIM + col] = res;
}

// ---------------- launch ----------------
extern "C" void kernel_launch(void* const* d_in, const int* in_sizes, int n_in,
                              void* d_out, int out_size) {
    const float* coords = (const float*)d_in[0];
    const int*   labels = (const int*)d_in[1];
    const float* W1 = (const float*)d_in[2];
    const float* b1 = (const float*)d_in[3];
    const float* W2 = (const float*)d_in[4];
    const float* b2 = (const float*)d_in[5];
    const float* W3 = (const float*)d_in[6];
    const float* b3 = (const float*)d_in[7];
    const float* Wa = (const float*)d_in[8];
    const float* ba = (const float*)d_in[9];
    const float* lng = (const float*)d_in[10];
    const float* lnb = (const float*)d_in[11];
    const float* Wb = (const float*)d_in[12];
    const float* bb = (const float*)d_in[13];
    float* out = (float*)d_out;

    pack_c4_kernel<<<(BATCH * NPTS + 255) / 256, 256>>>(coords);
    zero_kernel<<<(BATCH * NSEG * DIM + 255) / 256, 256>>>();
    count_kernel<<<(BATCH * NPTS + 255) / 256, 256>>>(labels);
    knn_kernel<<<dim3(NPTS / 8, BATCH), 256>>>();
    mlp12_kernel<<<BATCH * NPTS / 4, 256>>>(W1, b1, W2, b2);
    gemm_pc_kernel<<<dim3(DIM / 64, BATCH * NPTS / 64), 256>>>(W3, b3, labels, out);
    means_kernel<<<(BATCH * NSEG * DIM + 255) / 256, 256>>>();
    gemm_a_kernel<<<dim3(DIM / 64, BATCH * NSEG / 64), 256>>>(Wa, ba);
    ln_relu_kernel<<<BATCH * NSEG, 256>>>(lng, lnb);
    gemm_b_kernel<<<dim3(DIM / 64, BATCH * NSEG / 64), 256>>>(Wb, bb);
    mix_kernel<<<dim3(DIM / 256, BATCH * NPTS), 256>>>(labels, out);
}

// round 7
// speedup vs baseline: 1.0634x; 1.0634x over previous
#include <cuda_runtime.h>
#include <math.h>
#include <float.h>

#define BATCH 2
#define NPTS  8192
#define KNB   16
#define NSEG  256
#define DIM   768
#define H1DIM 128
#define H2DIM 256

typedef unsigned long long u64;

// ---------------- f32x2 packed-FMA helpers (sm_100+ PTX) ----------------
__device__ __forceinline__ void ffma2(u64& d, u64 a, u64 b) {
    asm("fma.rn.f32x2 %0, %1, %2, %0;" : "+l"(d) : "l"(a), "l"(b));
}
__device__ __forceinline__ u64 pack2(float lo, float hi) {
    u64 r; asm("mov.b64 %0, {%1, %2};" : "=l"(r) : "f"(lo), "f"(hi)); return r;
}
__device__ __forceinline__ void unpack2(u64 v, float& lo, float& hi) {
    asm("mov.b64 {%0, %1}, %2;" : "=f"(lo), "=f"(hi) : "l"(v));
}

// ---------------- device scratch ----------------
static __device__ float4 g_c4[BATCH * NPTS];
static __device__ int    g_idx[BATCH * NPTS * KNB];
static __device__ float  g_hbar[BATCH * NPTS * H2DIM];
static __device__ float  g_sums[BATCH * NSEG * DIM];
static __device__ float  g_counts[BATCH * NSEG];
static __device__ float  g_means[BATCH * NSEG * DIM];
static __device__ float  g_lin1[BATCH * NSEG * DIM];
static __device__ float  g_lnr[BATCH * NSEG * DIM];
static __device__ float  g_agg[BATCH * NSEG * DIM];

// ---------------- small prep kernels ----------------
__global__ void pack_c4_kernel(const float* __restrict__ coords) {
    int i = blockIdx.x * 256 + threadIdx.x;
    if (i >= BATCH * NPTS) return;
    float x = coords[3 * i + 0];
    float y = coords[3 * i + 1];
    float z = coords[3 * i + 2];
    g_c4[i] = make_float4(x, y, z, x * x + y * y + z * z);
}

__global__ void zero_kernel() {
    int i = blockIdx.x * 256 + threadIdx.x;
    if (i < BATCH * NSEG * DIM) g_sums[i] = 0.0f;
    if (i < BATCH * NSEG) g_counts[i] = 0.0f;
}

__global__ void count_kernel(const int* __restrict__ labels) {
    int i = blockIdx.x * 256 + threadIdx.x;
    if (i >= BATCH * NPTS) return;
    atomicAdd(&g_counts[(i >> 13) * NSEG + labels[i]], 1.0f);
}

// ---------------- KNN: branchless FMNMX top-k (values) + ballot index collect ----------------
__global__ void knn_kernel() {
    __shared__ float4 tile[2048];
    int b = blockIdx.y;
    int warp = threadIdx.x >> 5;
    int lane = threadIdx.x & 31;
    int q = blockIdx.x * 8 + warp;

    float4 qc = g_c4[b * NPTS + q];
    float ax = -2.0f * qc.x, ay = -2.0f * qc.y, az = -2.0f * qc.z;

    const float INF = __int_as_float(0x7f800000);
    float kd[16];
#pragma unroll
    for (int u = 0; u < 16; u++) kd[u] = INF;

    // ---- pass 1: per-lane sorted top-16 values ----
    for (int t = 0; t < 4; t++) {
        __syncthreads();
        for (int i = threadIdx.x; i < 2048; i += 256)
            tile[i] = g_c4[b * NPTS + t * 2048 + i];
        __syncthreads();
#pragma unroll 4
        for (int it = 0; it < 64; it++) {
            float4 c = tile[it * 32 + lane];
            float key = fmaf(ax, c.x, fmaf(ay, c.y, fmaf(az, c.z, c.w)));
            if (__any_sync(0xffffffffu, key < kd[15])) {
                // branchless sorted insert (no-op when key >= kd[15])
#pragma unroll
                for (int u = 15; u > 0; u--)
                    kd[u] = fminf(kd[u], fmaxf(key, kd[u - 1]));
                kd[0] = fminf(kd[0], key);
            }
        }
    }

    // ---- merge: find global 16th smallest value (threshold) ----
    float thresh = 0.0f;
    for (int r = 0; r < 16; r++) {
        float m = kd[0];
#pragma unroll
        for (int off = 16; off > 0; off >>= 1)
            m = fminf(m, __shfl_xor_sync(0xffffffffu, m, off));
        unsigned ball = __ballot_sync(0xffffffffu, kd[0] == m);
        if (lane == (__ffs(ball) - 1)) {
#pragma unroll
            for (int u = 0; u < 15; u++) kd[u] = kd[u + 1];
            kd[15] = INF;
        }
        thresh = m;
    }

    // ---- pass 2: collect indices with key <= thresh, in index order ----
    int cnt = 0;
    int base = (b * NPTS + q) * KNB;
    for (int t = 0; t < 4; t++) {
        __syncthreads();
        for (int i = threadIdx.x; i < 2048; i += 256)
            tile[i] = g_c4[b * NPTS + t * 2048 + i];
        __syncthreads();
#pragma unroll 4
        for (int it = 0; it < 64; it++) {
            float4 c = tile[it * 32 + lane];
            float key = fmaf(ax, c.x, fmaf(ay, c.y, fmaf(az, c.z, c.w)));
            bool p = (key <= thresh);
            unsigned ball = __ballot_sync(0xffffffffu, p);
            if (p) {
                int pos = cnt + __popc(ball & ((1u << lane) - 1u));
                if (pos < KNB) g_idx[base + pos] = t * 2048 + it * 32 + lane;
            }
            cnt += __popc(ball);
        }
    }
}

// ---------------- fused features + MLP layers 1,2 + mean over K (FFMA2) ----------------
// block = 256 threads, 4 points (64 rows of (point,k))
__global__ void mlp12_kernel(const float* __restrict__ W1, const float* __restrict__ b1,
                             const float* __restrict__ W2, const float* __restrict__ b2) {
    __shared__ __align__(16) float h1t[H1DIM * 64];   // [channel][row], 32 KB
    __shared__ __align__(16) u64   w2d[16 * 64];      // duplicated (w,w) subtile, 8 KB
    __shared__ float w1s[7 * H1DIM];
    __shared__ float b1s[H1DIM];
    __shared__ float b2s[H2DIM];
    int tid = threadIdx.x;
    int blk = blockIdx.x;

    for (int i = tid; i < 7 * H1DIM; i += 256) w1s[i] = W1[i];
    if (tid < H1DIM) b1s[tid] = b1[tid];
    b2s[tid] = b2[tid];
    __syncthreads();

    // phase 1: features + layer1
    {
        int row = tid >> 2;
        int qq  = tid & 3;
        int pg  = blk * 4 + (row >> 4);
        int bb  = pg >> 13;
        int k   = row & 15;
        int nb  = g_idx[pg * KNB + k];
        float4 sc = g_c4[pg];
        float4 nc = g_c4[bb * NPTS + nb];
        float dx = nc.x - sc.x, dy = nc.y - sc.y, dz = nc.z - sc.z;
        float f0 = sqrtf(dx * dx + dy * dy + dz * dz);
        float f4 = atan2f(dy, dx);
        float f5 = atan2f(dz, dx);
        float f6 = atan2f(dz, dy);
        int cbase = qq * 32;
#pragma unroll 8
        for (int c0 = 0; c0 < 32; c0++) {
            int c = cbase + c0;
            float acc = b1s[c];
            acc = fmaf(f0, w1s[c], acc);
            acc = fmaf(dx, w1s[1 * H1DIM + c], acc);
            acc = fmaf(dy, w1s[2 * H1DIM + c], acc);
            acc = fmaf(dz, w1s[3 * H1DIM + c], acc);
            acc = fmaf(f4, w1s[4 * H1DIM + c], acc);
            acc = fmaf(f5, w1s[5 * H1DIM + c], acc);
            acc = fmaf(f6, w1s[6 * H1DIM + c], acc);
            h1t[c * 64 + row] = fmaxf(acc, 0.0f);
        }
    }

    // phase 2: h2 = relu(h1 @ W2 + b2), mean over k, FFMA2 inner loop
    int ci = tid >> 4;   // 0..15 col group (4 cols)
    int ri = tid & 15;   // 0..15 row group (4 rows)
    for (int t = 0; t < 4; t++) {
        u64 acc2[2][4];
#pragma unroll
        for (int p = 0; p < 2; p++)
#pragma unroll
            for (int j = 0; j < 4; j++) acc2[p][j] = 0ull;

        for (int ks = 0; ks < 8; ks++) {
            __syncthreads();
            for (int i = tid; i < 1024; i += 256) {
                int kk = i >> 6, c = i & 63;
                float w = W2[(ks * 16 + kk) * H2DIM + t * 64 + c];
                w2d[i] = pack2(w, w);
            }
            __syncthreads();
#pragma unroll
            for (int kk = 0; kk < 16; kk++) {
                ulonglong2 av = *(const ulonglong2*)&h1t[(ks * 16 + kk) * 64 + ri * 4];
                ulonglong2 b0 = *(const ulonglong2*)&w2d[kk * 64 + ci * 4];
                ulonglong2 b1v = *(const ulonglong2*)&w2d[kk * 64 + ci * 4 + 2];
                ffma2(acc2[0][0], av.x, b0.x);
                ffma2(acc2[0][1], av.x, b0.y);
                ffma2(acc2[0][2], av.x, b1v.x);
                ffma2(acc2[0][3], av.x, b1v.y);
                ffma2(acc2[1][0], av.y, b0.x);
                ffma2(acc2[1][1], av.y, b0.y);
                ffma2(acc2[1][2], av.y, b1v.x);
                ffma2(acc2[1][3], av.y, b1v.y);
            }
        }
        // epilogue: unpack, bias+relu, sum 4 rows + shuffle over ri&3
        float s[4];
#pragma unroll
        for (int j = 0; j < 4; j++) {
            float x0, x1, x2, x3;
            unpack2(acc2[0][j], x0, x1);
            unpack2(acc2[1][j], x2, x3);
            float bv = b2s[t * 64 + ci * 4 + j];
            s[j] = fmaxf(x0 + bv, 0.0f) + fmaxf(x1 + bv, 0.0f)
                 + fmaxf(x2 + bv, 0.0f) + fmaxf(x3 + bv, 0.0f);
        }
#pragma unroll
        for (int j = 0; j < 4; j++) {
            s[j] += __shfl_xor_sync(0xffffffffu, s[j], 1);
            s[j] += __shfl_xor_sync(0xffffffffu, s[j], 2);
        }
        if ((ri & 3) == 0) {
            int p = blk * 4 + (ri >> 2);
            const float inv = 1.0f / 16.0f;
            float4 o = make_float4(s[0] * inv, s[1] * inv, s[2] * inv, s[3] * inv);
            *(float4*)&g_hbar[p * H2DIM + t * 64 + ci * 4] = o;
        }
    }
}

// ---------------- generic 64x64 tiled GEMM core (FFMA2) ----------------
struct GemmSmem {
    __align__(16) float At[16][68];   // A transposed [kk][row]
    __align__(16) u64   Bd[16 * 64];  // B duplicated (w,w)
};

__device__ __forceinline__ void gemm_tile(const float* __restrict__ A,
                                          const float* __restrict__ Bm,
                                          int Kk, int Nn, int r0, int c0,
                                          GemmSmem* sm, u64 acc2[2][4]) {
    int tid = threadIdx.x, tx = tid & 15, ty = tid >> 4;
    for (int k0 = 0; k0 < Kk; k0 += 16) {
        __syncthreads();
        for (int i = tid; i < 1024; i += 256) {
            int r = i >> 4, kk = i & 15;
            sm->At[kk][r] = A[(r0 + r) * Kk + k0 + kk];
        }
        for (int i = tid; i < 1024; i += 256) {
            int kk = i >> 6, c = i & 63;
            float w = Bm[(k0 + kk) * Nn + c0 + c];
            sm->Bd[i] = pack2(w, w);
        }
        __syncthreads();
#pragma unroll
        for (int kk = 0; kk < 16; kk++) {
            ulonglong2 av = *(const ulonglong2*)&sm->At[kk][ty * 4];
            ulonglong2 b0 = *(const ulonglong2*)&sm->Bd[kk * 64 + tx * 4];
            ulonglong2 b1v = *(const ulonglong2*)&sm->Bd[kk * 64 + tx * 4 + 2];
            ffma2(acc2[0][0], av.x, b0.x);
            ffma2(acc2[0][1], av.x, b0.y);
            ffma2(acc2[0][2], av.x, b1v.x);
            ffma2(acc2[0][3], av.x, b1v.y);
            ffma2(acc2[1][0], av.y, b0.x);
            ffma2(acc2[1][1], av.y, b0.y);
            ffma2(acc2[1][2], av.y, b1v.x);
            ffma2(acc2[1][3], av.y, b1v.y);
        }
    }
}

__device__ __forceinline__ void unpack_acc(u64 acc2[2][4], float ov[4][4]) {
#pragma unroll
    for (int p = 0; p < 2; p++)
#pragma unroll
        for (int j = 0; j < 4; j++)
            unpack2(acc2[p][j], ov[2 * p][j], ov[2 * p + 1][j]);
}

// pc = hbar @ W3 + b3 ; scatter-add into segment sums
__global__ void gemm_pc_kernel(const float* __restrict__ W3, const float* __restrict__ b3,
                               const int* __restrict__ labels, float* __restrict__ out) {
    __shared__ GemmSmem sm;
    int r0 = blockIdx.y * 64, c0 = blockIdx.x * 64;
    u64 acc2[2][4] = {{0ull,0ull,0ull,0ull},{0ull,0ull,0ull,0ull}};
    gemm_tile(g_hbar, W3, H2DIM, DIM, r0, c0, &sm, acc2);
    float ov[4][4];
    unpack_acc(acc2, ov);
    int tid = threadIdx.x, tx = tid & 15, ty = tid >> 4;
#pragma unroll
    for (int i = 0; i < 4; i++) {
        int row = r0 + ty * 4 + i;
        int lbl = labels[row];
        int base = (row >> 13) * NSEG * DIM + lbl * DIM;
#pragma unroll
        for (int j = 0; j < 4; j++) {
            int col = c0 + tx * 4 + j;
            float v = ov[i][j] + b3[col];
            out[row * DIM + col] = v;
            atomicAdd(&g_sums[base + col], v);
        }
    }
}

__global__ void means_kernel() {
    int i = blockIdx.x * 256 + threadIdx.x;
    if (i >= BATCH * NSEG * DIM) return;
    g_means[i] = g_sums[i] / fmaxf(g_counts[i / DIM], 1.0f);
}

__global__ void gemm_a_kernel(const float* __restrict__ Wa, const float* __restrict__ ba) {
    __shared__ GemmSmem sm;
    int r0 = blockIdx.y * 64, c0 = blockIdx.x * 64;
    u64 acc2[2][4] = {{0ull,0ull,0ull,0ull},{0ull,0ull,0ull,0ull}};
    gemm_tile(g_means, Wa, DIM, DIM, r0, c0, &sm, acc2);
    float ov[4][4];
    unpack_acc(acc2, ov);
    int tid = threadIdx.x, tx = tid & 15, ty = tid >> 4;
#pragma unroll
    for (int i = 0; i < 4; i++)
#pragma unroll
        for (int j = 0; j < 4; j++) {
            int row = r0 + ty * 4 + i, col = c0 + tx * 4 + j;
            g_lin1[row * DIM + col] = ov[i][j] + ba[col];
        }
}

__global__ void ln_relu_kernel(const float* __restrict__ lng, const float* __restrict__ lnb) {
    int row = blockIdx.x, tid = threadIdx.x;
    __shared__ float sh[8];
    const float* a = &g_lin1[row * DIM];
    float s = 0.0f;
    for (int c = tid; c < DIM; c += 256) s += a[c];
#pragma unroll
    for (int o = 16; o > 0; o >>= 1) s += __shfl_xor_sync(0xffffffffu, s, o);
    if ((tid & 31) == 0) sh[tid >> 5] = s;
    __syncthreads();
    float mu = 0.0f;
#pragma unroll
    for (int w = 0; w < 8; w++) mu += sh[w];
    mu *= (1.0f / DIM);
    __syncthreads();
    float vs = 0.0f;
    for (int c = tid; c < DIM; c += 256) { float d = a[c] - mu; vs += d * d; }
#pragma unroll
    for (int o = 16; o > 0; o >>= 1) vs += __shfl_xor_sync(0xffffffffu, vs, o);
    if ((tid & 31) == 0) sh[tid >> 5] = vs;
    __syncthreads();
    float var = 0.0f;
#pragma unroll
    for (int w = 0; w < 8; w++) var += sh[w];
    var *= (1.0f / DIM);
    float rstd = rsqrtf(var + 1e-5f);
    for (int c = tid; c < DIM; c += 256) {
        float x = (a[c] - mu) * rstd * lng[c] + lnb[c];
        g_lnr[row * DIM + c] = fmaxf(x, 0.0f);
    }
}

__global__ void gemm_b_kernel(const float* __restrict__ Wb, const float* __restrict__ bb) {
    __shared__ GemmSmem sm;
    int r0 = blockIdx.y * 64, c0 = blockIdx.x * 64;
    u64 acc2[2][4] = {{0ull,0ull,0ull,0ull},{0ull,0ull,0ull,0ull}};
    gemm_tile(g_lnr, Wb, DIM, DIM, r0, c0, &sm, acc2);
    float ov[4][4];
    unpack_acc(acc2, ov);
    int tid = threadIdx.x, tx = tid & 15, ty = tid >> 4;
#pragma unroll
    for (int i = 0; i < 4; i++)
#pragma unroll
        for (int j = 0; j < 4; j++) {
            int row = r0 + ty * 4 + i, col = c0 + tx * 4 + j;
            g_agg[row * DIM + col] = ov[i][j] + bb[col];
        }
}

__global__ void mix_kernel(const int* __restrict__ labels, float* __restrict__ out) {
    int row = blockIdx.y;
    int col = blockIdx.x * 256 + threadIdx.x;
    int lbl = labels[row];
    int bs = (row >> 13) * NSEG + lbl;
    float pc = out[row * DIM + col];
    float res = pc;
    if (g_counts[bs] >= 2.0f)
        res = 0.8f * pc + 0.2f * g_agg[bs * DIM + col];
    out[row * DIM + col] = res;
}

// ---------------- launch ----------------
extern "C" void kernel_launch(void* const* d_in, const int* in_sizes, int n_in,
                              void* d_out, int out_size) {
    const float* coords = (const float*)d_in[0];
    const int*   labels = (const int*)d_in[1];
    const float* W1 = (const float*)d_in[2];
    const float* b1 = (const float*)d_in[3];
    const float* W2 = (const float*)d_in[4];
    const float* b2 = (const float*)d_in[5];
    const float* W3 = (const float*)d_in[6];
    const float* b3 = (const float*)d_in[7];
    const float* Wa = (const float*)d_in[8];
    const float* ba = (const float*)d_in[9];
    const float* lng = (const float*)d_in[10];
    const float* lnb = (const float*)d_in[11];
    const float* Wb = (const float*)d_in[12];
    const float* bb = (const float*)d_in[13];
    float* out = (float*)d_out;

    pack_c4_kernel<<<(BATCH * NPTS + 255) / 256, 256>>>(coords);
    zero_kernel<<<(BATCH * NSEG * DIM + 255) / 256, 256>>>();
    count_kernel<<<(BATCH * NPTS + 255) / 256, 256>>>(labels);
    knn_kernel<<<dim3(NPTS / 8, BATCH), 256>>>();
    mlp12_kernel<<<BATCH * NPTS / 4, 256>>>(W1, b1, W2, b2);
    gemm_pc_kernel<<<dim3(DIM / 64, BATCH * NPTS / 64), 256>>>(W3, b3, labels, out);
    means_kernel<<<(BATCH * NSEG * DIM + 255) / 256, 256>>>();
    gemm_a_kernel<<<dim3(DIM / 64, BATCH * NSEG / 64), 256>>>(Wa, ba);
    ln_relu_kernel<<<BATCH * NSEG, 256>>>(lng, lnb);
    gemm_b_kernel<<<dim3(DIM / 64, BATCH * NSEG / 64), 256>>>(Wb, bb);
    mix_kernel<<<dim3(DIM / 256, BATCH * NPTS), 256>>>(labels, out);
}

// round 9
// speedup vs baseline: 1.5281x; 1.4369x over previous
#include <cuda_runtime.h>
#include <math.h>
#include <float.h>

#define BATCH 2
#define NPTS  8192
#define KNB   16
#define NSEG  256
#define DIM   768
#define H1DIM 128
#define H2DIM 256

typedef unsigned long long u64;

// ---------------- f32x2 packed-FMA helpers ----------------
__device__ __forceinline__ void ffma2(u64& d, u64 a, u64 b) {
    asm("fma.rn.f32x2 %0, %1, %2, %0;" : "+l"(d) : "l"(a), "l"(b));
}
__device__ __forceinline__ u64 pack2(float lo, float hi) {
    u64 r; asm("mov.b64 %0, {%1, %2};" : "=l"(r) : "f"(lo), "f"(hi)); return r;
}
__device__ __forceinline__ void unpack2(u64 v, float& lo, float& hi) {
    asm("mov.b64 {%0, %1}, %2;" : "=f"(lo), "=f"(hi) : "l"(v));
}

// ---------------- device scratch ----------------
static __device__ float4 g_c4[BATCH * NPTS];
static __device__ int    g_idx[BATCH * NPTS * KNB];
static __device__ __align__(16) float g_hbar[BATCH * NPTS * H2DIM];
static __device__ float  g_sums[BATCH * NSEG * DIM];
static __device__ float  g_counts[BATCH * NSEG];
static __device__ float  g_means[BATCH * NSEG * DIM];
static __device__ float  g_lin1[BATCH * NSEG * DIM];
static __device__ float  g_lnr[BATCH * NSEG * DIM];
static __device__ float  g_agg[BATCH * NSEG * DIM];

// ---------------- small prep kernels ----------------
__global__ void pack_c4_kernel(const float* __restrict__ coords) {
    int i = blockIdx.x * 256 + threadIdx.x;
    if (i >= BATCH * NPTS) return;
    float x = coords[3 * i + 0];
    float y = coords[3 * i + 1];
    float z = coords[3 * i + 2];
    g_c4[i] = make_float4(x, y, z, x * x + y * y + z * z);
}

__global__ void zero_kernel() {
    int i = blockIdx.x * 256 + threadIdx.x;
    if (i < BATCH * NSEG * DIM) g_sums[i] = 0.0f;
    if (i < BATCH * NSEG) g_counts[i] = 0.0f;
}

__global__ void count_kernel(const int* __restrict__ labels) {
    int i = blockIdx.x * 256 + threadIdx.x;
    if (i >= BATCH * NPTS) return;
    atomicAdd(&g_counts[(i >> 13) * NSEG + labels[i]], 1.0f);
}

// ---------------- KNN (round-7 version, alu-bound, 306us) ----------------
__global__ void knn_kernel() {
    __shared__ float4 tile[2048];
    int b = blockIdx.y;
    int warp = threadIdx.x >> 5;
    int lane = threadIdx.x & 31;
    int q = blockIdx.x * 8 + warp;

    float4 qc = g_c4[b * NPTS + q];
    float ax = -2.0f * qc.x, ay = -2.0f * qc.y, az = -2.0f * qc.z;

    const float INF = __int_as_float(0x7f800000);
    float kd[16];
#pragma unroll
    for (int u = 0; u < 16; u++) kd[u] = INF;

    for (int t = 0; t < 4; t++) {
        __syncthreads();
        for (int i = threadIdx.x; i < 2048; i += 256)
            tile[i] = g_c4[b * NPTS + t * 2048 + i];
        __syncthreads();
#pragma unroll 4
        for (int it = 0; it < 64; it++) {
            float4 c = tile[it * 32 + lane];
            float key = fmaf(ax, c.x, fmaf(ay, c.y, fmaf(az, c.z, c.w)));
            if (__any_sync(0xffffffffu, key < kd[15])) {
#pragma unroll
                for (int u = 15; u > 0; u--)
                    kd[u] = fminf(kd[u], fmaxf(key, kd[u - 1]));
                kd[0] = fminf(kd[0], key);
            }
        }
    }

    float thresh = 0.0f;
    for (int r = 0; r < 16; r++) {
        float m = kd[0];
#pragma unroll
        for (int off = 16; off > 0; off >>= 1)
            m = fminf(m, __shfl_xor_sync(0xffffffffu, m, off));
        unsigned ball = __ballot_sync(0xffffffffu, kd[0] == m);
        if (lane == (__ffs(ball) - 1)) {
#pragma unroll
            for (int u = 0; u < 15; u++) kd[u] = kd[u + 1];
            kd[15] = INF;
        }
        thresh = m;
    }

    int cnt = 0;
    int base = (b * NPTS + q) * KNB;
    for (int t = 0; t < 4; t++) {
        __syncthreads();
        for (int i = threadIdx.x; i < 2048; i += 256)
            tile[i] = g_c4[b * NPTS + t * 2048 + i];
        __syncthreads();
#pragma unroll 4
        for (int it = 0; it < 64; it++) {
            float4 c = tile[it * 32 + lane];
            float key = fmaf(ax, c.x, fmaf(ay, c.y, fmaf(az, c.z, c.w)));
            bool p = (key <= thresh);
            unsigned ball = __ballot_sync(0xffffffffu, p);
            if (p) {
                int pos = cnt + __popc(ball & ((1u << lane) - 1u));
                if (pos < KNB) g_idx[base + pos] = t * 2048 + it * 32 + lane;
            }
            cnt += __popc(ball);
        }
    }
}

// ---------------- fused features + MLP layers 1,2 + mean over K ----------------
// block = 256 threads, 4 points (64 rows of (point,k))
// phase 2: FFMA2 with 8x8 register tile, x2 packed along columns
__global__ void __launch_bounds__(256, 2)
mlp12_kernel(const float* __restrict__ W1, const float* __restrict__ b1,
             const float* __restrict__ W2, const float* __restrict__ b2) {
    __shared__ __align__(16) float h1t[H1DIM * 64];   // [k][row], 32 KB
    __shared__ __align__(16) float w2s[8 * H2DIM];    // [kk][col] chunk, 8 KB
    __shared__ float w1s[7 * H1DIM];
    __shared__ float b1s[H1DIM];
    __shared__ float b2s[H2DIM];
    int tid = threadIdx.x;
    int blk = blockIdx.x;

    for (int i = tid; i < 7 * H1DIM; i += 256) w1s[i] = W1[i];
    if (tid < H1DIM) b1s[tid] = b1[tid];
    b2s[tid] = b2[tid];
    __syncthreads();

    // phase 1: features + layer1
    {
        int row = tid >> 2;
        int qq  = tid & 3;
        int pg  = blk * 4 + (row >> 4);
        int bb  = pg >> 13;
        int k   = row & 15;
        int nb  = g_idx[pg * KNB + k];
        float4 sc = g_c4[pg];
        float4 nc = g_c4[bb * NPTS + nb];
        float dx = nc.x - sc.x, dy = nc.y - sc.y, dz = nc.z - sc.z;
        float f0 = sqrtf(dx * dx + dy * dy + dz * dz);
        float f4 = atan2f(dy, dx);
        float f5 = atan2f(dz, dx);
        float f6 = atan2f(dz, dy);
        int cbase = qq * 32;
#pragma unroll 8
        for (int c0 = 0; c0 < 32; c0++) {
            int c = cbase + c0;
            float acc = b1s[c];
            acc = fmaf(f0, w1s[c], acc);
            acc = fmaf(dx, w1s[1 * H1DIM + c], acc);
            acc = fmaf(dy, w1s[2 * H1DIM + c], acc);
            acc = fmaf(dz, w1s[3 * H1DIM + c], acc);
            acc = fmaf(f4, w1s[4 * H1DIM + c], acc);
            acc = fmaf(f5, w1s[5 * H1DIM + c], acc);
            acc = fmaf(f6, w1s[6 * H1DIM + c], acc);
            h1t[c * 64 + row] = fmaxf(acc, 0.0f);
        }
    }

    // phase 2: h2 = relu(h1 @ W2 + b2), mean over k
    int lane = tid & 31, w = tid >> 5;
    int rg  = lane >> 2;          // 0..7 : rows rg*8 .. rg*8+7
    int cgl = lane & 3;
    int cg  = w * 4 + cgl;        // 0..31: cols cg*8 .. cg*8+7

    u64 acc2[8][4];
#pragma unroll
    for (int r = 0; r < 8; r++)
#pragma unroll
        for (int j = 0; j < 4; j++) acc2[r][j] = 0ull;

    for (int ks = 0; ks < 16; ks++) {   // k chunks of 8
        __syncthreads();
        for (int i = tid; i < 512; i += 256)
            ((float4*)w2s)[i] = ((const float4*)(W2 + (ks * 8 + (i >> 6)) * H2DIM))[i & 63];
        __syncthreads();
#pragma unroll
        for (int kk = 0; kk < 8; kk++) {
            const float* hrow = &h1t[(ks * 8 + kk) * 64 + rg * 8];
            float4 a0 = *(const float4*)hrow;
            float4 a1 = *(const float4*)(hrow + 4);
            u64 ap[8];
            ap[0] = pack2(a0.x, a0.x); ap[1] = pack2(a0.y, a0.y);
            ap[2] = pack2(a0.z, a0.z); ap[3] = pack2(a0.w, a0.w);
            ap[4] = pack2(a1.x, a1.x); ap[5] = pack2(a1.y, a1.y);
            ap[6] = pack2(a1.z, a1.z); ap[7] = pack2(a1.w, a1.w);
            ulonglong2 bv0 = *(const ulonglong2*)&w2s[kk * H2DIM + cg * 8];
            ulonglong2 bv1 = *(const ulonglong2*)&w2s[kk * H2DIM + cg * 8 + 4];
#pragma unroll
            for (int r = 0; r < 8; r++) {
                ffma2(acc2[r][0], ap[r], bv0.x);
                ffma2(acc2[r][1], ap[r], bv0.y);
                ffma2(acc2[r][2], ap[r], bv1.x);
                ffma2(acc2[r][3], ap[r], bv1.y);
            }
        }
    }

    // epilogue: bias + relu per row, sum 8 rows, combine with partner (rg^1), mean
    float sums[8];
#pragma unroll
    for (int j = 0; j < 4; j++) {
        float blo = b2s[cg * 8 + 2 * j];
        float bhi = b2s[cg * 8 + 2 * j + 1];
        float slo = 0.0f, shi = 0.0f;
#pragma unroll
        for (int r = 0; r < 8; r++) {
            float lo, hi;
            unpack2(acc2[r][j], lo, hi);
            slo += fmaxf(lo + blo, 0.0f);
            shi += fmaxf(hi + bhi, 0.0f);
        }
        sums[2 * j] = slo; sums[2 * j + 1] = shi;
    }
#pragma unroll
    for (int j = 0; j < 8; j++)
        sums[j] += __shfl_xor_sync(0xffffffffu, sums[j], 4);
    if ((rg & 1) == 0) {
        int p = blk * 4 + (rg >> 1);
        const float inv = 1.0f / 16.0f;
        float4 o0 = make_float4(sums[0] * inv, sums[1] * inv, sums[2] * inv, sums[3] * inv);
        float4 o1 = make_float4(sums[4] * inv, sums[5] * inv, sums[6] * inv, sums[7] * inv);
        *(float4*)&g_hbar[p * H2DIM + cg * 8]     = o0;
        *(float4*)&g_hbar[p * H2DIM + cg * 8 + 4] = o1;
    }
}

// ---------------- gemm_pc: pc = hbar @ W3 + b3, FFMA2 8x8, fused scatter ----------------
__global__ void __launch_bounds__(256, 2)
gemm_pc_kernel(const float* __restrict__ W3, const float* __restrict__ b3,
               const int* __restrict__ labels, float* __restrict__ out) {
    __shared__ __align__(16) float As[16 * 64];    // [kk][row], 4 KB
    __shared__ __align__(16) float Bs[16 * 256];   // [kk][col], 16 KB
    __shared__ int   lbls[64];
    __shared__ float b3s[256];
    int tid = threadIdx.x;
    int r0 = blockIdx.y * 64;
    int c0 = blockIdx.x * 256;

    if (tid < 64) lbls[tid] = labels[r0 + tid];
    b3s[tid] = b3[c0 + tid];

    int lane = tid & 31, w = tid >> 5;
    int rg  = lane >> 2;
    int cgl = lane & 3;
    int cg  = w * 4 + cgl;

    u64 acc2[8][4];
#pragma unroll
    for (int r = 0; r < 8; r++)
#pragma unroll
        for (int j = 0; j < 4; j++) acc2[r][j] = 0ull;

    int arow = tid & 63, akq = tid >> 6;
    for (int k0 = 0; k0 < H2DIM; k0 += 16) {
        __syncthreads();
        {
            float4 av = *(const float4*)&g_hbar[(r0 + arow) * H2DIM + k0 + akq * 4];
            As[(akq * 4 + 0) * 64 + arow] = av.x;
            As[(akq * 4 + 1) * 64 + arow] = av.y;
            As[(akq * 4 + 2) * 64 + arow] = av.z;
            As[(akq * 4 + 3) * 64 + arow] = av.w;
        }
        for (int i = tid; i < 1024; i += 256)
            ((float4*)Bs)[i] = *(const float4*)&W3[(k0 + (i >> 6)) * DIM + c0 + (i & 63) * 4];
        __syncthreads();
#pragma unroll
        for (int kk = 0; kk < 16; kk++) {
            const float* arow_p = &As[kk * 64 + rg * 8];
            float4 a0 = *(const float4*)arow_p;
            float4 a1 = *(const float4*)(arow_p + 4);
            u64 ap[8];
            ap[0] = pack2(a0.x, a0.x); ap[1] = pack2(a0.y, a0.y);
            ap[2] = pack2(a0.z, a0.z); ap[3] = pack2(a0.w, a0.w);
            ap[4] = pack2(a1.x, a1.x); ap[5] = pack2(a1.y, a1.y);
            ap[6] = pack2(a1.z, a1.z); ap[7] = pack2(a1.w, a1.w);
            ulonglong2 bv0 = *(const ulonglong2*)&Bs[kk * 256 + cg * 8];
            ulonglong2 bv1 = *(const ulonglong2*)&Bs[kk * 256 + cg * 8 + 4];
#pragma unroll
            for (int r = 0; r < 8; r++) {
                ffma2(acc2[r][0], ap[r], bv0.x);
                ffma2(acc2[r][1], ap[r], bv0.y);
                ffma2(acc2[r][2], ap[r], bv1.x);
                ffma2(acc2[r][3], ap[r], bv1.y);
            }
        }
    }

    int bbase = (r0 >> 13) * NSEG * DIM;
#pragma unroll
    for (int i = 0; i < 8; i++) {
        int row = r0 + rg * 8 + i;
        int sbase = bbase + lbls[rg * 8 + i] * DIM;
#pragma unroll
        for (int j = 0; j < 4; j++) {
            float lo, hi;
            unpack2(acc2[i][j], lo, hi);
            int cc = cg * 8 + 2 * j;
            float v0 = lo + b3s[cc];
            float v1 = hi + b3s[cc + 1];
            int col = c0 + cc;
            out[row * DIM + col]     = v0;
            out[row * DIM + col + 1] = v1;
            atomicAdd(&g_sums[sbase + col],     v0);
            atomicAdd(&g_sums[sbase + col + 1], v1);
        }
    }
}

__global__ void means_kernel() {
    int i = blockIdx.x * 256 + threadIdx.x;
    if (i >= BATCH * NSEG * DIM) return;
    g_means[i] = g_sums[i] / fmaxf(g_counts[i / DIM], 1.0f);
}

// ---------------- scalar 64x64 tiled GEMM (round-6 form) for small GEMMs ----------------
struct GemmSmem { float As[64][17]; float Bs[16][64]; };

__device__ __forceinline__ void gemm_tile(const float* __restrict__ A,
                                          const float* __restrict__ Bm,
                                          int Kk, int Nn, int r0, int c0,
                                          GemmSmem* sm, float acc[4][4]) {
    int tid = threadIdx.x, tx = tid & 15, ty = tid >> 4;
    for (int k0 = 0; k0 < Kk; k0 += 16) {
        for (int i = tid; i < 1024; i += 256) {
            int r = i >> 4, kk = i & 15;
            sm->As[r][kk] = A[(r0 + r) * Kk + k0 + kk];
        }
        for (int i = tid; i < 1024; i += 256) {
            int kk = i >> 6, c = i & 63;
            sm->Bs[kk][c] = Bm[(k0 + kk) * Nn + c0 + c];
        }
        __syncthreads();
#pragma unroll
        for (int kk = 0; kk < 16; kk++) {
            float a0 = sm->As[ty * 4 + 0][kk];
            float a1 = sm->As[ty * 4 + 1][kk];
            float a2 = sm->As[ty * 4 + 2][kk];
            float a3 = sm->As[ty * 4 + 3][kk];
            float4 bf = *(const float4*)&sm->Bs[kk][tx * 4];
            acc[0][0] += a0 * bf.x; acc[0][1] += a0 * bf.y; acc[0][2] += a0 * bf.z; acc[0][3] += a0 * bf.w;
            acc[1][0] += a1 * bf.x; acc[1][1] += a1 * bf.y; acc[1][2] += a1 * bf.z; acc[1][3] += a1 * bf.w;
            acc[2][0] += a2 * bf.x; acc[2][1] += a2 * bf.y; acc[2][2] += a2 * bf.z; acc[2][3] += a2 * bf.w;
            acc[3][0] += a3 * bf.x; acc[3][1] += a3 * bf.y; acc[3][2] += a3 * bf.z; acc[3][3] += a3 * bf.w;
        }
        __syncthreads();
    }
}

__global__ void gemm_a_kernel(const float* __restrict__ Wa, const float* __restrict__ ba) {
    __shared__ GemmSmem sm;
    int r0 = blockIdx.y * 64, c0 = blockIdx.x * 64;
    float acc[4][4];
#pragma unroll
    for (int i = 0; i < 4; i++)
#pragma unroll
        for (int j = 0; j < 4; j++) acc[i][j] = 0.0f;
    gemm_tile(g_means, Wa, DIM, DIM, r0, c0, &sm, acc);
    int tid = threadIdx.x, tx = tid & 15, ty = tid >> 4;
#pragma unroll
    for (int i = 0; i < 4; i++)
#pragma unroll
        for (int j = 0; j < 4; j++) {
            int row = r0 + ty * 4 + i, col = c0 + tx * 4 + j;
            g_lin1[row * DIM + col] = acc[i][j] + ba[col];
        }
}

__global__ void ln_relu_kernel(const float* __restrict__ lng, const float* __restrict__ lnb) {
    int row = blockIdx.x, tid = threadIdx.x;
    __shared__ float sh[8];
    const float* a = &g_lin1[row * DIM];
    float s = 0.0f;
    for (int c = tid; c < DIM; c += 256) s += a[c];
#pragma unroll
    for (int o = 16; o > 0; o >>= 1) s += __shfl_xor_sync(0xffffffffu, s, o);
    if ((tid & 31) == 0) sh[tid >> 5] = s;
    __syncthreads();
    float mu = 0.0f;
#pragma unroll
    for (int w = 0; w < 8; w++) mu += sh[w];
    mu *= (1.0f / DIM);
    __syncthreads();
    float vs = 0.0f;
    for (int c = tid; c < DIM; c += 256) { float d = a[c] - mu; vs += d * d; }
#pragma unroll
    for (int o = 16; o > 0; o >>= 1) vs += __shfl_xor_sync(0xffffffffu, vs, o);
    if ((tid & 31) == 0) sh[tid >> 5] = vs;
    __syncthreads();
    float var = 0.0f;
#pragma unroll
    for (int w = 0; w < 8; w++) var += sh[w];
    var *= (1.0f / DIM);
    float rstd = rsqrtf(var + 1e-5f);
    for (int c = tid; c < DIM; c += 256) {
        float x = (a[c] - mu) * rstd * lng[c] + lnb[c];
        g_lnr[row * DIM + c] = fmaxf(x, 0.0f);
    }
}

__global__ void gemm_b_kernel(const float* __restrict__ Wb, const float* __restrict__ bb) {
    __shared__ GemmSmem sm;
    int r0 = blockIdx.y * 64, c0 = blockIdx.x * 64;
    float acc[4][4];
#pragma unroll
    for (int i = 0; i < 4; i++)
#pragma unroll
        for (int j = 0; j < 4; j++) acc[i][j] = 0.0f;
    gemm_tile(g_lnr, Wb, DIM, DIM, r0, c0, &sm, acc);
    int tid = threadIdx.x, tx = tid & 15, ty = tid >> 4;
#pragma unroll
    for (int i = 0; i < 4; i++)
#pragma unroll
        for (int j = 0; j < 4; j++) {
            int row = r0 + ty * 4 + i, col = c0 + tx * 4 + j;
            g_agg[row * DIM + col] = acc[i][j] + bb[col];
        }
}

__global__ void mix_kernel(const int* __restrict__ labels, float* __restrict__ out) {
    int row = blockIdx.y;
    int col = blockIdx.x * 256 + threadIdx.x;
    int lbl = labels[row];
    int bs = (row >> 13) * NSEG + lbl;
    float pc = out[row * DIM + col];
    float res = pc;
    if (g_counts[bs] >= 2.0f)
        res = 0.8f * pc + 0.2f * g_agg[bs * DIM + col];
    out[row * DIM + col] = res;
}

// ---------------- launch ----------------
extern "C" void kernel_launch(void* const* d_in, const int* in_sizes, int n_in,
                              void* d_out, int out_size) {
    const float* coords = (const float*)d_in[0];
    const int*   labels = (const int*)d_in[1];
    const float* W1 = (const float*)d_in[2];
    const float* b1 = (const float*)d_in[3];
    const float* W2 = (const float*)d_in[4];
    const float* b2 = (const float*)d_in[5];
    const float* W3 = (const float*)d_in[6];
    const float* b3 = (const float*)d_in[7];
    const float* Wa = (const float*)d_in[8];
    const float* ba = (const float*)d_in[9];
    const float* lng = (const float*)d_in[10];
    const float* lnb = (const float*)d_in[11];
    const float* Wb = (const float*)d_in[12];
    const float* bb = (const float*)d_in[13];
    float* out = (float*)d_out;

    pack_c4_kernel<<<(BATCH * NPTS + 255) / 256, 256>>>(coords);
    zero_kernel<<<(BATCH * NSEG * DIM + 255) / 256, 256>>>();
    count_kernel<<<(BATCH * NPTS + 255) / 256, 256>>>(labels);
    knn_kernel<<<dim3(NPTS / 8, BATCH), 256>>>();
    mlp12_kernel<<<BATCH * NPTS / 4, 256>>>(W1, b1, W2, b2);
    gemm_pc_kernel<<<dim3(DIM / 256, BATCH * NPTS / 64), 256>>>(W3, b3, labels, out);
    means_kernel<<<(BATCH * NSEG * DIM + 255) / 256, 256>>>();
    gemm_a_kernel<<<dim3(DIM / 64, BATCH * NSEG / 64), 256>>>(Wa, ba);
    ln_relu_kernel<<<BATCH * NSEG, 256>>>(lng, lnb);
    gemm_b_kernel<<<dim3(DIM / 64, BATCH * NSEG / 64), 256>>>(Wb, bb);
    mix_kernel<<<dim3(DIM / 256, BATCH * NPTS), 256>>>(labels, out);
}

// round 11
// speedup vs baseline: 1.7047x; 1.1155x over previous
#include <cuda_runtime.h>
#include <math.h>
#include <float.h>

#define BATCH 2
#define NPTS  8192
#define KNB   16
#define NSEG  256
#define DIM   768
#define H1DIM 128
#define H2DIM 256

typedef unsigned long long u64;

// ---------------- f32x2 packed-FMA helpers ----------------
__device__ __forceinline__ void ffma2(u64& d, u64 a, u64 b) {
    asm("fma.rn.f32x2 %0, %1, %2, %0;" : "+l"(d) : "l"(a), "l"(b));
}
__device__ __forceinline__ u64 pack2(float lo, float hi) {
    u64 r; asm("mov.b64 %0, {%1, %2};" : "=l"(r) : "f"(lo), "f"(hi)); return r;
}
__device__ __forceinline__ void unpack2(u64 v, float& lo, float& hi) {
    asm("mov.b64 {%0, %1}, %2;" : "=f"(lo), "=f"(hi) : "l"(v));
}

// ---------------- device scratch ----------------
static __device__ float4 g_c4[BATCH * NPTS];
static __device__ int    g_idx[BATCH * NPTS * KNB];
static __device__ __align__(16) float g_hbar[BATCH * NPTS * H2DIM];
static __device__ float  g_sums[BATCH * NSEG * DIM];
static __device__ float  g_counts[BATCH * NSEG];
static __device__ float  g_means[BATCH * NSEG * DIM];
static __device__ float  g_lin1[BATCH * NSEG * DIM];
static __device__ float  g_lnr[BATCH * NSEG * DIM];
static __device__ float  g_agg[BATCH * NSEG * DIM];

// ---------------- prep: pack coords + zero accumulators ----------------
__global__ void prep_kernel(const float* __restrict__ coords) {
    int i = blockIdx.x * 256 + threadIdx.x;
    if (i < BATCH * NSEG * DIM) g_sums[i] = 0.0f;
    if (i < BATCH * NSEG) g_counts[i] = 0.0f;
    if (i < BATCH * NPTS) {
        float x = coords[3 * i + 0];
        float y = coords[3 * i + 1];
        float z = coords[3 * i + 2];
        g_c4[i] = make_float4(x, y, z, x * x + y * y + z * z);
    }
}

__global__ void count_kernel(const int* __restrict__ labels) {
    int i = blockIdx.x * 256 + threadIdx.x;
    if (i >= BATCH * NPTS) return;
    atomicAdd(&g_counts[(i >> 13) * NSEG + labels[i]], 1.0f);
}

// ---------------- KNN: warp-cooperative sorted queue + ballot index collect ----------------
__global__ void knn_kernel() {
    __shared__ float4 tile[2048];
    int b = blockIdx.y;
    int warp = threadIdx.x >> 5;
    int lane = threadIdx.x & 31;
    int q = blockIdx.x * 8 + warp;

    float4 qc = g_c4[b * NPTS + q];
    float ax = -2.0f * qc.x, ay = -2.0f * qc.y, az = -2.0f * qc.z;

    const float INF  = __int_as_float(0x7f800000);
    const float NINF = __int_as_float(0xff800000);

    // warp-distributed sorted list: lane l holds the l-th smallest key seen
    float S = INF;
    float thresh = INF;   // = S[15], maintained incrementally

    // ---- pass 1: find exact 16th-smallest key ----
    for (int t = 0; t < 4; t++) {
        __syncthreads();
        for (int i = threadIdx.x; i < 2048; i += 256)
            tile[i] = g_c4[b * NPTS + t * 2048 + i];
        __syncthreads();
#pragma unroll 4
        for (int it = 0; it < 64; it++) {
            float4 c = tile[it * 32 + lane];
            float key = fmaf(ax, c.x, fmaf(ay, c.y, fmaf(az, c.z, c.w)));
            unsigned ball = __ballot_sync(0xffffffffu, key < thresh);
            while (ball) {
                int src = __ffs(ball) - 1;
                ball &= ball - 1;
                float k = __shfl_sync(0xffffffffu, key, src);
                // warp-wide sorted insert (drops current max, lane 31)
                float up = __shfl_up_sync(0xffffffffu, S, 1);
                if (lane == 0) up = NINF;
                S = (S < k) ? S : fmaxf(k, up);
                thresh = __shfl_sync(0xffffffffu, S, 15);
            }
        }
    }

    // ---- pass 2: collect indices with key <= thresh, in index order ----
    int cnt = 0;
    int base = (b * NPTS + q) * KNB;
    for (int t = 0; t < 4; t++) {
        __syncthreads();
        for (int i = threadIdx.x; i < 2048; i += 256)
            tile[i] = g_c4[b * NPTS + t * 2048 + i];
        __syncthreads();
#pragma unroll 4
        for (int it = 0; it < 64; it++) {
            float4 c = tile[it * 32 + lane];
            float key = fmaf(ax, c.x, fmaf(ay, c.y, fmaf(az, c.z, c.w)));
            bool p = (key <= thresh);
            unsigned ball = __ballot_sync(0xffffffffu, p);
            if (p) {
                int pos = cnt + __popc(ball & ((1u << lane) - 1u));
                if (pos < KNB) g_idx[base + pos] = t * 2048 + it * 32 + lane;
            }
            cnt += __popc(ball);
        }
    }
}

// ---------------- fused features + MLP layers 1,2 + mean over K ----------------
// block = 256 threads, 4 points (64 rows of (point,k))
// dynamic smem: h1t (32KB) + union{ phase1: w1s+b1s | phase2: w2s 16KB }
__global__ void __launch_bounds__(256, 2)
mlp12_kernel(const float* __restrict__ W1, const float* __restrict__ b1,
             const float* __restrict__ W2, const float* __restrict__ b2) {
    extern __shared__ __align__(16) float dynsm[];
    float* h1t = dynsm;                   // 8192 floats: [k][row]
    float* w1s = dynsm + 8192;            // 896 floats  (phase 1)
    float* b1s = dynsm + 8192 + 896;      // 128 floats  (phase 1)
    float* w2s = dynsm + 8192;            // 4096 floats (phase 2, overlaps w1s/b1s)
    int tid = threadIdx.x;
    int blk = blockIdx.x;

    for (int i = tid; i < 7 * H1DIM; i += 256) w1s[i] = W1[i];
    if (tid < H1DIM) b1s[tid] = b1[tid];
    __syncthreads();

    // phase 1: features + layer1
    {
        int row = tid >> 2;
        int qq  = tid & 3;
        int pg  = blk * 4 + (row >> 4);
        int bb  = pg >> 13;
        int k   = row & 15;
        int nb  = g_idx[pg * KNB + k];
        float4 sc = g_c4[pg];
        float4 nc = g_c4[bb * NPTS + nb];
        float dx = nc.x - sc.x, dy = nc.y - sc.y, dz = nc.z - sc.z;
        float f0 = sqrtf(dx * dx + dy * dy + dz * dz);
        float f4 = atan2f(dy, dx);
        float f5 = atan2f(dz, dx);
        float f6 = atan2f(dz, dy);
        int cbase = qq * 32;
#pragma unroll 8
        for (int c0 = 0; c0 < 32; c0++) {
            int c = cbase + c0;
            float acc = b1s[c];
            acc = fmaf(f0, w1s[c], acc);
            acc = fmaf(dx, w1s[1 * H1DIM + c], acc);
            acc = fmaf(dy, w1s[2 * H1DIM + c], acc);
            acc = fmaf(dz, w1s[3 * H1DIM + c], acc);
            acc = fmaf(f4, w1s[4 * H1DIM + c], acc);
            acc = fmaf(f5, w1s[5 * H1DIM + c], acc);
            acc = fmaf(f6, w1s[6 * H1DIM + c], acc);
            h1t[c * 64 + row] = fmaxf(acc, 0.0f);
        }
    }

    // phase 2: h2 = relu(h1 @ W2 + b2), mean over k; FFMA2 8x8, x2 along cols
    int lane = tid & 31, w = tid >> 5;
    int rg  = lane >> 2;          // 0..7 : rows rg*8 .. rg*8+7
    int cgl = lane & 3;
    int cg  = w * 4 + cgl;        // 0..31: cols cg*8 .. cg*8+7

    u64 acc2[8][4];
#pragma unroll
    for (int r = 0; r < 8; r++)
#pragma unroll
        for (int j = 0; j < 4; j++) acc2[r][j] = 0ull;

    for (int ks = 0; ks < 8; ks++) {   // k chunks of 16
        __syncthreads();
        for (int i = tid; i < 1024; i += 256)
            ((float4*)w2s)[i] = ((const float4*)(W2 + (ks * 16 + (i >> 6)) * H2DIM))[i & 63];
        __syncthreads();
#pragma unroll
        for (int kk = 0; kk < 16; kk++) {
            const float* hrow = &h1t[(ks * 16 + kk) * 64 + rg * 8];
            float4 a0 = *(const float4*)hrow;
            float4 a1 = *(const float4*)(hrow + 4);
            u64 ap[8];
            ap[0] = pack2(a0.x, a0.x); ap[1] = pack2(a0.y, a0.y);
            ap[2] = pack2(a0.z, a0.z); ap[3] = pack2(a0.w, a0.w);
            ap[4] = pack2(a1.x, a1.x); ap[5] = pack2(a1.y, a1.y);
            ap[6] = pack2(a1.z, a1.z); ap[7] = pack2(a1.w, a1.w);
            ulonglong2 bv0 = *(const ulonglong2*)&w2s[kk * H2DIM + cg * 8];
            ulonglong2 bv1 = *(const ulonglong2*)&w2s[kk * H2DIM + cg * 8 + 4];
#pragma unroll
            for (int r = 0; r < 8; r++) {
                ffma2(acc2[r][0], ap[r], bv0.x);
                ffma2(acc2[r][1], ap[r], bv0.y);
                ffma2(acc2[r][2], ap[r], bv1.x);
                ffma2(acc2[r][3], ap[r], bv1.y);
            }
        }
    }

    // epilogue: bias + relu per row, sum 8 rows, combine with partner (rg^1), mean
    float4 bl0 = *(const float4*)&b2[cg * 8];
    float4 bl1 = *(const float4*)&b2[cg * 8 + 4];
    float bias[8] = {bl0.x, bl0.y, bl0.z, bl0.w, bl1.x, bl1.y, bl1.z, bl1.w};
    float sums[8];
#pragma unroll
    for (int j = 0; j < 4; j++) {
        float blo = bias[2 * j];
        float bhi = bias[2 * j + 1];
        float slo = 0.0f, shi = 0.0f;
#pragma unroll
        for (int r = 0; r < 8; r++) {
            float lo, hi;
            unpack2(acc2[r][j], lo, hi);
            slo += fmaxf(lo + blo, 0.0f);
            shi += fmaxf(hi + bhi, 0.0f);
        }
        sums[2 * j] = slo; sums[2 * j + 1] = shi;
    }
#pragma unroll
    for (int j = 0; j < 8; j++)
        sums[j] += __shfl_xor_sync(0xffffffffu, sums[j], 4);
    if ((rg & 1) == 0) {
        int p = blk * 4 + (rg >> 1);
        const float inv = 1.0f / 16.0f;
        float4 o0 = make_float4(sums[0] * inv, sums[1] * inv, sums[2] * inv, sums[3] * inv);
        float4 o1 = make_float4(sums[4] * inv, sums[5] * inv, sums[6] * inv, sums[7] * inv);
        *(float4*)&g_hbar[p * H2DIM + cg * 8]     = o0;
        *(float4*)&g_hbar[p * H2DIM + cg * 8 + 4] = o1;
    }
}

// ---------------- gemm_pc: pc = hbar @ W3 + b3, FFMA2 8x8, fused scatter ----------------
__global__ void __launch_bounds__(256, 2)
gemm_pc_kernel(const float* __restrict__ W3, const float* __restrict__ b3,
               const int* __restrict__ labels, float* __restrict__ out) {
    __shared__ __align__(16) float As[16 * 64];    // [kk][row], 4 KB
    __shared__ __align__(16) float Bs[16 * 256];   // [kk][col], 16 KB
    __shared__ int   lbls[64];
    __shared__ float b3s[256];
    int tid = threadIdx.x;
    int r0 = blockIdx.y * 64;
    int c0 = blockIdx.x * 256;

    if (tid < 64) lbls[tid] = labels[r0 + tid];
    b3s[tid] = b3[c0 + tid];

    int lane = tid & 31, w = tid >> 5;
    int rg  = lane >> 2;
    int cgl = lane & 3;
    int cg  = w * 4 + cgl;

    u64 acc2[8][4];
#pragma unroll
    for (int r = 0; r < 8; r++)
#pragma unroll
        for (int j = 0; j < 4; j++) acc2[r][j] = 0ull;

    int arow = tid & 63, akq = tid >> 6;
    for (int k0 = 0; k0 < H2DIM; k0 += 16) {
        __syncthreads();
        {
            float4 av = *(const float4*)&g_hbar[(r0 + arow) * H2DIM + k0 + akq * 4];
            As[(akq * 4 + 0) * 64 + arow] = av.x;
            As[(akq * 4 + 1) * 64 + arow] = av.y;
            As[(akq * 4 + 2) * 64 + arow] = av.z;
            As[(akq * 4 + 3) * 64 + arow] = av.w;
        }
        for (int i = tid; i < 1024; i += 256)
            ((float4*)Bs)[i] = *(const float4*)&W3[(k0 + (i >> 6)) * DIM + c0 + (i & 63) * 4];
        __syncthreads();
#pragma unroll
        for (int kk = 0; kk < 16; kk++) {
            const float* arow_p = &As[kk * 64 + rg * 8];
            float4 a0 = *(const float4*)arow_p;
            float4 a1 = *(const float4*)(arow_p + 4);
            u64 ap[8];
            ap[0] = pack2(a0.x, a0.x); ap[1] = pack2(a0.y, a0.y);
            ap[2] = pack2(a0.z, a0.z); ap[3] = pack2(a0.w, a0.w);
            ap[4] = pack2(a1.x, a1.x); ap[5] = pack2(a1.y, a1.y);
            ap[6] = pack2(a1.z, a1.z); ap[7] = pack2(a1.w, a1.w);
            ulonglong2 bv0 = *(const ulonglong2*)&Bs[kk * 256 + cg * 8];
            ulonglong2 bv1 = *(const ulonglong2*)&Bs[kk * 256 + cg * 8 + 4];
#pragma unroll
            for (int r = 0; r < 8; r++) {
                ffma2(acc2[r][0], ap[r], bv0.x);
                ffma2(acc2[r][1], ap[r], bv0.y);
                ffma2(acc2[r][2], ap[r], bv1.x);
                ffma2(acc2[r][3], ap[r], bv1.y);
            }
        }
    }

    int bbase = (r0 >> 13) * NSEG * DIM;
#pragma unroll
    for (int i = 0; i < 8; i++) {
        int row = r0 + rg * 8 + i;
        int sbase = bbase + lbls[rg * 8 + i] * DIM;
#pragma unroll
        for (int j = 0; j < 4; j++) {
            float lo, hi;
            unpack2(acc2[i][j], lo, hi);
            int cc = cg * 8 + 2 * j;
            float v0 = lo + b3s[cc];
            float v1 = hi + b3s[cc + 1];
            int col = c0 + cc;
            out[row * DIM + col]     = v0;
            out[row * DIM + col + 1] = v1;
            atomicAdd(&g_sums[sbase + col],     v0);
            atomicAdd(&g_sums[sbase + col + 1], v1);
        }
    }
}

__global__ void means_kernel() {
    int i = blockIdx.x * 256 + threadIdx.x;
    if (i >= BATCH * NSEG * DIM) return;
    g_means[i] = g_sums[i] / fmaxf(g_counts[i / DIM], 1.0f);
}

// ---------------- scalar 64x64 tiled GEMM for small GEMMs ----------------
struct GemmSmem { float As[64][17]; float Bs[16][64]; };

__device__ __forceinline__ void gemm_tile(const float* __restrict__ A,
                                          const float* __restrict__ Bm,
                                          int Kk, int Nn, int r0, int c0,
                                          GemmSmem* sm, float acc[4][4]) {
    int tid = threadIdx.x, tx = tid & 15, ty = tid >> 4;
    for (int k0 = 0; k0 < Kk; k0 += 16) {
        for (int i = tid; i < 1024; i += 256) {
            int r = i >> 4, kk = i & 15;
            sm->As[r][kk] = A[(r0 + r) * Kk + k0 + kk];
        }
        for (int i = tid; i < 1024; i += 256) {
            int kk = i >> 6, c = i & 63;
            sm->Bs[kk][c] = Bm[(k0 + kk) * Nn + c0 + c];
        }
        __syncthreads();
#pragma unroll
        for (int kk = 0; kk < 16; kk++) {
            float a0 = sm->As[ty * 4 + 0][kk];
            float a1 = sm->As[ty * 4 + 1][kk];
            float a2 = sm->As[ty * 4 + 2][kk];
            float a3 = sm->As[ty * 4 + 3][kk];
            float4 bf = *(const float4*)&sm->Bs[kk][tx * 4];
            acc[0][0] += a0 * bf.x; acc[0][1] += a0 * bf.y; acc[0][2] += a0 * bf.z; acc[0][3] += a0 * bf.w;
            acc[1][0] += a1 * bf.x; acc[1][1] += a1 * bf.y; acc[1][2] += a1 * bf.z; acc[1][3] += a1 * bf.w;
            acc[2][0] += a2 * bf.x; acc[2][1] += a2 * bf.y; acc[2][2] += a2 * bf.z; acc[2][3] += a2 * bf.w;
            acc[3][0] += a3 * bf.x; acc[3][1] += a3 * bf.y; acc[3][2] += a3 * bf.z; acc[3][3] += a3 * bf.w;
        }
        __syncthreads();
    }
}

__global__ void gemm_a_kernel(const float* __restrict__ Wa, const float* __restrict__ ba) {
    __shared__ GemmSmem sm;
    int r0 = blockIdx.y * 64, c0 = blockIdx.x * 64;
    float acc[4][4];
#pragma unroll
    for (int i = 0; i < 4; i++)
#pragma unroll
        for (int j = 0; j < 4; j++) acc[i][j] = 0.0f;
    gemm_tile(g_means, Wa, DIM, DIM, r0, c0, &sm, acc);
    int tid = threadIdx.x, tx = tid & 15, ty = tid >> 4;
#pragma unroll
    for (int i = 0; i < 4; i++)
#pragma unroll
        for (int j = 0; j < 4; j++) {
            int row = r0 + ty * 4 + i, col = c0 + tx * 4 + j;
            g_lin1[row * DIM + col] = acc[i][j] + ba[col];
        }
}

__global__ void ln_relu_kernel(const float* __restrict__ lng, const float* __restrict__ lnb) {
    int row = blockIdx.x, tid = threadIdx.x;
    __shared__ float sh[8];
    const float* a = &g_lin1[row * DIM];
    float s = 0.0f;
    for (int c = tid; c < DIM; c += 256) s += a[c];
#pragma unroll
    for (int o = 16; o > 0; o >>= 1) s += __shfl_xor_sync(0xffffffffu, s, o);
    if ((tid & 31) == 0) sh[tid >> 5] = s;
    __syncthreads();
    float mu = 0.0f;
#pragma unroll
    for (int w = 0; w < 8; w++) mu += sh[w];
    mu *= (1.0f / DIM);
    __syncthreads();
    float vs = 0.0f;
    for (int c = tid; c < DIM; c += 256) { float d = a[c] - mu; vs += d * d; }
#pragma unroll
    for (int o = 16; o > 0; o >>= 1) vs += __shfl_xor_sync(0xffffffffu, vs, o);
    if ((tid & 31) == 0) sh[tid >> 5] = vs;
    __syncthreads();
    float var = 0.0f;
#pragma unroll
    for (int w = 0; w < 8; w++) var += sh[w];
    var *= (1.0f / DIM);
    float rstd = rsqrtf(var + 1e-5f);
    for (int c = tid; c < DIM; c += 256) {
        float x = (a[c] - mu) * rstd * lng[c] + lnb[c];
        g_lnr[row * DIM + c] = fmaxf(x, 0.0f);
    }
}

__global__ void gemm_b_kernel(const float* __restrict__ Wb, const float* __restrict__ bb) {
    __shared__ GemmSmem sm;
    int r0 = blockIdx.y * 64, c0 = blockIdx.x * 64;
    float acc[4][4];
#pragma unroll
    for (int i = 0; i < 4; i++)
#pragma unroll
        for (int j = 0; j < 4; j++) acc[i][j] = 0.0f;
    gemm_tile(g_lnr, Wb, DIM, DIM, r0, c0, &sm, acc);
    int tid = threadIdx.x, tx = tid & 15, ty = tid >> 4;
#pragma unroll
    for (int i = 0; i < 4; i++)
#pragma unroll
        for (int j = 0; j < 4; j++) {
            int row = r0 + ty * 4 + i, col = c0 + tx * 4 + j;
            g_agg[row * DIM + col] = acc[i][j] + bb[col];
        }
}

__global__ void mix_kernel(const int* __restrict__ labels, float* __restrict__ out) {
    int row = blockIdx.y;
    int col = blockIdx.x * 256 + threadIdx.x;
    int lbl = labels[row];
    int bs = (row >> 13) * NSEG + lbl;
    float pc = out[row * DIM + col];
    float res = pc;
    if (g_counts[bs] >= 2.0f)
        res = 0.8f * pc + 0.2f * g_agg[bs * DIM + col];
    out[row * DIM + col] = res;
}

// ---------------- launch ----------------
extern "C" void kernel_launch(void* const* d_in, const int* in_sizes, int n_in,
                              void* d_out, int out_size) {
    const float* coords = (const float*)d_in[0];
    const int*   labels = (const int*)d_in[1];
    const float* W1 = (const float*)d_in[2];
    const float* b1 = (const float*)d_in[3];
    const float* W2 = (const float*)d_in[4];
    const float* b2 = (const float*)d_in[5];
    const float* W3 = (const float*)d_in[6];
    const float* b3 = (const float*)d_in[7];
    const float* Wa = (const float*)d_in[8];
    const float* ba = (const float*)d_in[9];
    const float* lng = (const float*)d_in[10];
    const float* lnb = (const float*)d_in[11];
    const float* Wb = (const float*)d_in[12];
    const float* bb = (const float*)d_in[13];
    float* out = (float*)d_out;

    static bool attr_set = false;
    if (!attr_set) {
        cudaFuncSetAttribute(mlp12_kernel,
                             cudaFuncAttributeMaxDynamicSharedMemorySize, 49152);
        attr_set = true;
    }

    prep_kernel<<<(BATCH * NSEG * DIM + 255) / 256, 256>>>(coords);
    count_kernel<<<(BATCH * NPTS + 255) / 256, 256>>>(labels);
    knn_kernel<<<dim3(NPTS / 8, BATCH), 256>>>();
    mlp12_kernel<<<BATCH * NPTS / 4, 256, 49152>>>(W1, b1, W2, b2);
    gemm_pc_kernel<<<dim3(DIM / 256, BATCH * NPTS / 64), 256>>>(W3, b3, labels, out);
    means_kernel<<<(BATCH * NSEG * DIM + 255) / 256, 256>>>();
    gemm_a_kernel<<<dim3(DIM / 64, BATCH * NSEG / 64), 256>>>(Wa, ba);
    ln_relu_kernel<<<BATCH * NSEG, 256>>>(lng, lnb);
    gemm_b_kernel<<<dim3(DIM / 64, BATCH * NSEG / 64), 256>>>(Wb, bb);
    mix_kernel<<<dim3(DIM / 256, BATCH * NPTS), 256>>>(labels, out);
}